// round 2
// baseline (speedup 1.0000x reference)
#include <cuda_runtime.h>
#include <math.h>

#define NN 4096
#define EE 32768
#define BB 64
#define GG 10
#define ZW 4160   // 65 slices * 64

__device__ float g_out[NN*64];
__device__ float g_h[NN*64];
__device__ float g_hidden[EE*64];
__device__ float g_z[(size_t)NN*ZW];
__device__ float g_agg[NN*64];
__device__ float g_m[NN*64];
__device__ float g_m2[NN*64];
__device__ float g_s[NN*GG];
__device__ float g_inv[GG*64];
__device__ float g_shift[GG*64];
__device__ float g_colshift[64];
__device__ float g_gi[NN*192];
__device__ float g_gh[NN*192];
__device__ float g_pooled[BB*64];
__device__ float g_p[BB*64];
__device__ float g_invc[NN];
__device__ int   g_cnt[NN];
__device__ int   g_bcnt[BB];

// C[r,j] = act( rowscale[r]*base[r,j] + sum_k A[r,k]*B(k,j) + bias[j] ), 64 rows/block
template<int K, int J, int TC, bool BT, bool RELU, bool HASBASE>
__global__ void gemm_small(const float* __restrict__ A, const float* __restrict__ B,
                           const float* __restrict__ bias,
                           const float* __restrict__ base, const float* __restrict__ rowscale,
                           float* __restrict__ C)
{
    constexpr int KC = 32;
    constexpr int CG = J / TC;
    constexpr int RG = 256 / CG;
    constexpr int TR = 64 / RG;
    static_assert(RG * CG == 256, "");
    __shared__ float As[KC][68];
    __shared__ float Bs[KC][J];
    __shared__ float bsh[J];
    const int tid = threadIdx.x;
    const int n0 = blockIdx.x * 64;
    const int rg = tid / CG, cg = tid % CG;
    float acc[TR][TC];
#pragma unroll
    for (int i = 0; i < TR; i++)
#pragma unroll
        for (int j = 0; j < TC; j++) acc[i][j] = 0.f;
    for (int j = tid; j < J; j += 256) bsh[j] = bias[j];

    for (int kc = 0; kc < K; kc += KC) {
        __syncthreads();
        for (int idx = tid; idx < 64*KC; idx += 256) {
            int k = idx % KC, r = idx / KC;
            As[k][r] = A[(size_t)(n0 + r) * K + kc + k];
        }
        if (!BT) {
            for (int idx = tid; idx < KC*J; idx += 256) {
                int k = idx / J, j = idx % J;
                Bs[k][j] = B[(kc + k) * J + j];
            }
        } else {
            for (int idx = tid; idx < KC*J; idx += 256) {
                int j = idx / KC, k = idx % KC;
                Bs[k][j] = B[j * K + kc + k];
            }
        }
        __syncthreads();
#pragma unroll 8
        for (int k = 0; k < KC; k++) {
            float a[TR], b[TC];
#pragma unroll
            for (int i = 0; i < TR; i++) a[i] = As[k][rg*TR + i];
#pragma unroll
            for (int j = 0; j < TC; j++) b[j] = Bs[k][cg*TC + j];
#pragma unroll
            for (int i = 0; i < TR; i++)
#pragma unroll
                for (int j = 0; j < TC; j++)
                    acc[i][j] = fmaf(a[i], b[j], acc[i][j]);
        }
    }
#pragma unroll
    for (int i = 0; i < TR; i++) {
        int r = n0 + rg*TR + i;
#pragma unroll
        for (int j = 0; j < TC; j++) {
            int col = cg*TC + j;
            float v = acc[i][j] + bsh[col];
            if (HASBASE) v += rowscale[r] * base[(size_t)r*J + col];
            if (RELU) v = fmaxf(v, 0.f);
            C[(size_t)r*J + col] = v;
        }
    }
}

// z[n, slice, :] = out[n,:] @ w2[slice]  (slice 64 = b2 bias matrix)
__global__ void zgemm(const float* __restrict__ out, const float* __restrict__ w2,
                      const float* __restrict__ b2, float* __restrict__ z)
{
    __shared__ float As[64][68];
    __shared__ float Bs[64][64];
    const int tid = threadIdx.x;
    const int n0 = blockIdx.x * 64;
    const int d  = blockIdx.y;
    const float* Bsrc = (d < 64) ? (w2 + d * 4096) : b2;
    for (int idx = tid; idx < 4096; idx += 256) {
        As[idx % 64][idx / 64] = out[(size_t)(n0 + idx / 64) * 64 + (idx % 64)];
        Bs[idx / 64][idx % 64] = Bsrc[idx];
    }
    __syncthreads();
    const int rg = tid / 16, cg = tid % 16;
    float acc[4][4];
#pragma unroll
    for (int i = 0; i < 4; i++)
#pragma unroll
        for (int j = 0; j < 4; j++) acc[i][j] = 0.f;
#pragma unroll 8
    for (int k = 0; k < 64; k++) {
        float a[4], b[4];
#pragma unroll
        for (int i = 0; i < 4; i++) a[i] = As[k][rg*4 + i];
#pragma unroll
        for (int j = 0; j < 4; j++) b[j] = Bs[k][cg*4 + j];
#pragma unroll
        for (int i = 0; i < 4; i++)
#pragma unroll
            for (int j = 0; j < 4; j++)
                acc[i][j] = fmaf(a[i], b[j], acc[i][j]);
    }
#pragma unroll
    for (int i = 0; i < 4; i++) {
        float4 v = make_float4(acc[i][0], acc[i][1], acc[i][2], acc[i][3]);
        *(float4*)&z[(size_t)(n0 + rg*4 + i) * ZW + d*64 + cg*4] = v;
    }
}

__global__ void edge_msg(const float* __restrict__ hidden, const float* __restrict__ z,
                         const int* __restrict__ ei, float* __restrict__ agg)
{
    __shared__ float hsh[8][64];
    const int w = threadIdx.x >> 5, lane = threadIdx.x & 31;
    const int e = blockIdx.x * 8 + w;
    hsh[w][lane]      = hidden[(size_t)e*64 + lane];
    hsh[w][lane + 32] = hidden[(size_t)e*64 + 32 + lane];
    __syncwarp();
    const int src = ei[e], dst = ei[EE + e];
    const float2* zr = (const float2*)(z + (size_t)src * ZW);
    float ax = 0.f, ay = 0.f;
#pragma unroll 8
    for (int k = 0; k < 64; k++) {
        float h = hsh[w][k];
        float2 v = zr[k*32 + lane];
        ax = fmaf(h, v.x, ax);
        ay = fmaf(h, v.y, ay);
    }
    float2 vb = zr[64*32 + lane];
    ax += vb.x; ay += vb.y;
    atomicAdd(&agg[(size_t)dst*64 + 2*lane],     ax);
    atomicAdd(&agg[(size_t)dst*64 + 2*lane + 1], ay);
}

__global__ void count_dst(const int* __restrict__ ei, int* __restrict__ cnt) {
    int e = blockIdx.x * 256 + threadIdx.x;
    if (e < EE) atomicAdd(&cnt[ei[EE + e]], 1);
}
__global__ void count_batch(const int* __restrict__ batch, int* __restrict__ bcnt) {
    int n = blockIdx.x * 256 + threadIdx.x;
    if (n < NN) atomicAdd(&bcnt[batch[n]], 1);
}
__global__ void make_invc(const int* __restrict__ cnt, float* __restrict__ invc) {
    int n = blockIdx.x * 256 + threadIdx.x;
    if (n < NN) invc[n] = 1.f / (float)max(cnt[n], 1);
}

__global__ void dgn_softmax(const float* __restrict__ m, const float* __restrict__ lin,
                            float* __restrict__ s)
{
    __shared__ float msh[64][65];
    __shared__ float lsh[64*GG];
    const int t = threadIdx.x;      // 64 threads
    const int n0 = blockIdx.x * 64;
    for (int r = 0; r < 64; r++) msh[r][t] = m[(size_t)(n0 + r)*64 + t];
    for (int i = t; i < 64*GG; i += 64) lsh[i] = lin[i];
    __syncthreads();
    float logit[GG];
#pragma unroll
    for (int g = 0; g < GG; g++) logit[g] = 0.f;
    for (int k = 0; k < 64; k++) {
        float mv = msh[t][k];
#pragma unroll
        for (int g = 0; g < GG; g++) logit[g] = fmaf(mv, lsh[k*GG + g], logit[g]);
    }
    float mx = logit[0];
#pragma unroll
    for (int g = 1; g < GG; g++) mx = fmaxf(mx, logit[g]);
    float sum = 0.f;
#pragma unroll
    for (int g = 0; g < GG; g++) { logit[g] = expf(logit[g] - mx); sum += logit[g]; }
    float inv = 1.f / sum;
#pragma unroll
    for (int g = 0; g < GG; g++) s[(size_t)(n0 + t)*GG + g] = logit[g] * inv;
}

__global__ void dgn_stats(const float* __restrict__ m, const float* __restrict__ s,
                          const float* __restrict__ gamma, const float* __restrict__ beta,
                          float* __restrict__ inv, float* __restrict__ shift)
{
    const int c = blockIdx.x;               // 0..639
    const int g = c / 64, dd = c % 64;
    float sum = 0.f, sq = 0.f;
    for (int n = threadIdx.x; n < NN; n += 256) {
        float t = s[(size_t)n*GG + g] * m[(size_t)n*64 + dd];
        sum += t; sq = fmaf(t, t, sq);
    }
    __shared__ float rs[256], rq[256];
    rs[threadIdx.x] = sum; rq[threadIdx.x] = sq;
    __syncthreads();
    for (int st = 128; st > 0; st >>= 1) {
        if (threadIdx.x < st) { rs[threadIdx.x] += rs[threadIdx.x + st]; rq[threadIdx.x] += rq[threadIdx.x + st]; }
        __syncthreads();
    }
    if (threadIdx.x == 0) {
        float mu = rs[0] / (float)NN;
        float var = rq[0] / (float)NN - mu*mu;
        float iv = gamma[c] * rsqrtf(var + 1e-5f);
        inv[c] = iv;
        shift[c] = beta[c] - mu * iv;
    }
}

__global__ void dgn_colshift(const float* __restrict__ shift, float* __restrict__ colshift) {
    int dd = threadIdx.x;
    float sum = 0.f;
    for (int g = 0; g < GG; g++) sum += shift[g*64 + dd];
    colshift[dd] = sum;
}

__global__ void dgn_apply(const float* __restrict__ m, const float* __restrict__ s,
                          const float* __restrict__ inv, const float* __restrict__ colshift,
                          float* __restrict__ m2)
{
    __shared__ float ssh[64*GG];
    __shared__ float ish[GG*64];
    __shared__ float csh[64];
    const int t = threadIdx.x;
    const int n0 = blockIdx.x * 64;
    for (int i = t; i < 64*GG; i += 256) ssh[i] = s[(size_t)n0*GG + i];
    for (int i = t; i < GG*64; i += 256) ish[i] = inv[i];
    if (t < 64) csh[t] = colshift[t];
    __syncthreads();
    for (int idx = t; idx < 4096; idx += 256) {
        int nl = idx / 64, dd = idx % 64;
        float a = 0.f;
#pragma unroll
        for (int g = 0; g < GG; g++) a = fmaf(ssh[nl*GG + g], ish[g*64 + dd], a);
        float mv = m[(size_t)(n0 + nl)*64 + dd];
        float v = mv + 0.01f * fmaf(mv, a, csh[dd]);
        m2[(size_t)(n0 + nl)*64 + dd] = fmaxf(v, 0.f);
    }
}

__global__ void gru_gate(const float* __restrict__ gi, const float* __restrict__ gh,
                         float* __restrict__ h, float* __restrict__ out)
{
    int i = blockIdx.x * 256 + threadIdx.x;
    int n = i >> 6, dd = i & 63;
    const float* gin = gi + (size_t)n*192;
    const float* ghn = gh + (size_t)n*192;
    float r  = 1.f / (1.f + expf(-(gin[dd] + ghn[dd])));
    float zz = 1.f / (1.f + expf(-(gin[64+dd] + ghn[64+dd])));
    float nn = tanhf(fmaf(r, ghn[128+dd], gin[128+dd]));
    float hv = h[i];
    float hnew = fmaf(zz, hv, (1.f - zz) * nn);
    h[i] = hnew;
    out[i] = hnew + out[i];
}

__global__ void pool(const float* __restrict__ out, const int* __restrict__ batch,
                     float* __restrict__ pooled)
{
    int i = blockIdx.x * 256 + threadIdx.x;
    atomicAdd(&pooled[batch[i >> 6]*64 + (i & 63)], out[i]);
}
__global__ void pool_div(float* __restrict__ pooled, const int* __restrict__ bcnt) {
    int i = blockIdx.x * 256 + threadIdx.x;
    pooled[i] /= (float)max(bcnt[i >> 6], 1);
}
__global__ void post_fc(const float* __restrict__ pooled, const float* __restrict__ W,
                        const float* __restrict__ b, float* __restrict__ p)
{
    int i = blockIdx.x * 256 + threadIdx.x;   // BB*64
    int r = i >> 6, j = i & 63;
    float s = b[j];
    for (int k = 0; k < 64; k++) s = fmaf(pooled[r*64 + k], W[k*64 + j], s);
    p[i] = fmaxf(s, 0.f);
}
__global__ void final_y(const float* __restrict__ p, const float* __restrict__ outW,
                        const float* __restrict__ outb, float* __restrict__ y)
{
    int b = threadIdx.x;  // 64
    float s = outb[0];
    for (int k = 0; k < 64; k++) s = fmaf(p[b*64 + k], outW[k], s);
    y[b] = s;
}

__global__ void tkl_kernel(const float* __restrict__ preW, const float* __restrict__ preb,
                           const float* __restrict__ postW, const float* __restrict__ postb,
                           const float* __restrict__ outW, const float* __restrict__ outb,
                           float* __restrict__ dst)
{
    const double logc = log(0.15 * sqrt(2.0 * 3.14159265358979323846));
    double acc = 0.0;
    const int tid = threadIdx.x;
    const float* arrs[6] = {preW, preb, postW, postb, outW, outb};
    const int lens[6] = {128*64, 64, 64*64, 64, 64, 1};
    for (int a = 0; a < 6; a++)
        for (int i = tid; i < lens[a]; i += 256) {
            double v = (double)arrs[a][i] / 0.15;
            acc += 0.5 * v * v + logc;
        }
    __shared__ double red[256];
    red[tid] = acc;
    __syncthreads();
    for (int st = 128; st > 0; st >>= 1) {
        if (tid < st) red[tid] += red[tid + st];
        __syncthreads();
    }
    if (tid == 0) dst[0] = (float)red[0];
}

extern "C" void kernel_launch(void* const* d_in, const int* in_sizes, int n_in,
                              void* d_out, int out_size)
{
    const float* x         = (const float*)d_in[0];
    const float* edge_attr = (const float*)d_in[1];
    const float* pre_W     = (const float*)d_in[2];
    const float* pre_b     = (const float*)d_in[3];
    const float* edge_w1   = (const float*)d_in[4];
    const float* edge_b1   = (const float*)d_in[5];
    const float* edge_w2   = (const float*)d_in[6];
    const float* edge_b2   = (const float*)d_in[7];
    const float* root_w    = (const float*)d_in[8];
    const float* root_b    = (const float*)d_in[9];
    const float* gru_wih   = (const float*)d_in[10];
    const float* gru_whh   = (const float*)d_in[11];
    const float* gru_bih   = (const float*)d_in[12];
    const float* gru_bhh   = (const float*)d_in[13];
    const float* gn_lin    = (const float*)d_in[14];
    const float* gn_gamma  = (const float*)d_in[15];
    const float* gn_beta   = (const float*)d_in[16];
    const float* post_W    = (const float*)d_in[17];
    const float* post_b    = (const float*)d_in[18];
    const float* out_W     = (const float*)d_in[19];
    const float* out_b     = (const float*)d_in[20];
    const int*   ei        = (const int*)d_in[21];
    const int*   batch     = (const int*)d_in[22];
    float* y = (float*)d_out;

    float *p_out, *p_h, *p_hidden, *p_z, *p_agg, *p_m, *p_m2, *p_s, *p_inv, *p_shift,
          *p_colshift, *p_gi, *p_gh, *p_pooled, *p_p, *p_invc;
    int *p_cnt, *p_bcnt;
    cudaGetSymbolAddress((void**)&p_out, g_out);
    cudaGetSymbolAddress((void**)&p_h, g_h);
    cudaGetSymbolAddress((void**)&p_hidden, g_hidden);
    cudaGetSymbolAddress((void**)&p_z, g_z);
    cudaGetSymbolAddress((void**)&p_agg, g_agg);
    cudaGetSymbolAddress((void**)&p_m, g_m);
    cudaGetSymbolAddress((void**)&p_m2, g_m2);
    cudaGetSymbolAddress((void**)&p_s, g_s);
    cudaGetSymbolAddress((void**)&p_inv, g_inv);
    cudaGetSymbolAddress((void**)&p_shift, g_shift);
    cudaGetSymbolAddress((void**)&p_colshift, g_colshift);
    cudaGetSymbolAddress((void**)&p_gi, g_gi);
    cudaGetSymbolAddress((void**)&p_gh, g_gh);
    cudaGetSymbolAddress((void**)&p_pooled, g_pooled);
    cudaGetSymbolAddress((void**)&p_p, g_p);
    cudaGetSymbolAddress((void**)&p_invc, g_invc);
    cudaGetSymbolAddress((void**)&p_cnt, g_cnt);
    cudaGetSymbolAddress((void**)&p_bcnt, g_bcnt);

    cudaMemsetAsync(p_cnt, 0, NN * sizeof(int));
    cudaMemsetAsync(p_bcnt, 0, BB * sizeof(int));
    cudaMemsetAsync(p_pooled, 0, BB * 64 * sizeof(float));

    if (out_size >= 65)
        tkl_kernel<<<1, 256>>>(pre_W, pre_b, post_W, post_b, out_W, out_b, y + 64);

    count_dst<<<EE/256, 256>>>(ei, p_cnt);
    count_batch<<<NN/256, 256>>>(batch, p_bcnt);
    make_invc<<<NN/256, 256>>>(p_cnt, p_invc);

    // pre FC + relu; h = out
    gemm_small<128,64,4,false,true,false><<<NN/64, 256>>>(x, pre_W, pre_b, nullptr, nullptr, p_out);
    cudaMemcpyAsync(p_h, p_out, NN*64*sizeof(float), cudaMemcpyDeviceToDevice);

    for (int i = 0; i < 3; i++) {
        const float* w1 = edge_w1 + (size_t)i*64*64;
        const float* b1 = edge_b1 + (size_t)i*64;
        const float* w2 = edge_w2 + (size_t)i*64*4096;
        const float* b2 = edge_b2 + (size_t)i*4096;

        // hidden = relu(edge_attr @ w1 + b1)
        gemm_small<64,64,4,false,true,false><<<EE/64, 256>>>(edge_attr, w1, b1, nullptr, nullptr, p_hidden);
        // z[n,slice,:] = out @ w2_slice
        zgemm<<<dim3(NN/64, 65), 256>>>(p_out, w2, b2, p_z);
        // scatter messages
        cudaMemsetAsync(p_agg, 0, NN*64*sizeof(float));
        edge_msg<<<EE/8, 256>>>(p_hidden, p_z, ei, p_agg);
        // m = agg/cnt + out @ root_w + root_b
        gemm_small<64,64,4,false,false,true><<<NN/64, 256>>>(p_out, root_w + (size_t)i*4096,
            root_b + (size_t)i*64, p_agg, p_invc, p_m);
        // DiffGroupNorm + relu
        dgn_softmax<<<NN/64, 64>>>(p_m, gn_lin + (size_t)i*64*GG, p_s);
        dgn_stats<<<GG*64, 256>>>(p_m, p_s, gn_gamma + (size_t)i*GG*64, gn_beta + (size_t)i*GG*64, p_inv, p_shift);
        dgn_colshift<<<1, 64>>>(p_shift, p_colshift);
        dgn_apply<<<NN/64, 256>>>(p_m, p_s, p_inv, p_colshift, p_m2);
        // GRU
        gemm_small<64,192,12,true,false,false><<<NN/64, 256>>>(p_m2, gru_wih + (size_t)i*192*64,
            gru_bih + (size_t)i*192, nullptr, nullptr, p_gi);
        gemm_small<64,192,12,true,false,false><<<NN/64, 256>>>(p_h, gru_whh + (size_t)i*192*64,
            gru_bhh + (size_t)i*192, nullptr, nullptr, p_gh);
        gru_gate<<<NN*64/256, 256>>>(p_gi, p_gh, p_h, p_out);
    }

    pool<<<NN*64/256, 256>>>(p_out, batch, p_pooled);
    pool_div<<<BB*64/256, 256>>>(p_pooled, p_bcnt);
    post_fc<<<BB*64/256, 256>>>(p_pooled, post_W, post_b, p_p);
    final_y<<<1, 64>>>(p_p, out_W, out_b, y);
}

// round 3
// speedup vs baseline: 1.0246x; 1.0246x over previous
#include <cuda_runtime.h>
#include <math.h>

#define NN 4096
#define EE 32768
#define BB 64
#define GG 10
#define ZW 4160   // 65 slices * 64

__device__ float g_out[NN*64];
__device__ float g_h[NN*64];
__device__ float g_hidden[EE*64];
__device__ float g_z[(size_t)NN*ZW];
__device__ float g_agg[NN*64];
__device__ float g_m[NN*64];
__device__ float g_m2[NN*64];
__device__ float g_s[NN*GG];
__device__ float g_inv[GG*64];
__device__ float g_shift[GG*64];
__device__ float g_gi[NN*192];
__device__ float g_gh[NN*192];
__device__ float g_pooled[BB*64];
__device__ int   g_cntd[NN];      // in-degree (dst)
__device__ int   g_cnts[NN];      // out-degree (src)
__device__ int   g_bcnt[BB];
__device__ int   g_soff[NN+1];
__device__ int   g_cur[NN];
__device__ int   g_order[EE];

// C[r,j] = act( base[r,j]/cnt[r] + sum_k A[r,k]*B(k,j) + bias[j] ), 64 rows/block
template<int K, int J, int TC, bool BT, bool RELU, bool HASBASE, bool DUAL>
__global__ void gemm_small(const float* __restrict__ A, const float* __restrict__ B,
                           const float* __restrict__ bias,
                           const float* __restrict__ base, const int* __restrict__ cnt,
                           float* __restrict__ C, float* __restrict__ C2)
{
    constexpr int KC = 32;
    constexpr int CG = J / TC;
    constexpr int RG = 256 / CG;
    constexpr int TR = 64 / RG;
    static_assert(RG * CG == 256, "");
    __shared__ float As[KC][68];
    __shared__ float Bs[KC][J];
    __shared__ float bsh[J];
    const int tid = threadIdx.x;
    const int n0 = blockIdx.x * 64;
    const int rg = tid / CG, cg = tid % CG;
    float acc[TR][TC];
#pragma unroll
    for (int i = 0; i < TR; i++)
#pragma unroll
        for (int j = 0; j < TC; j++) acc[i][j] = 0.f;
    for (int j = tid; j < J; j += 256) bsh[j] = bias[j];

    for (int kc = 0; kc < K; kc += KC) {
        __syncthreads();
        for (int idx = tid; idx < 64*KC; idx += 256) {
            int k = idx % KC, r = idx / KC;
            As[k][r] = A[(size_t)(n0 + r) * K + kc + k];
        }
        if (!BT) {
            for (int idx = tid; idx < KC*J; idx += 256) {
                int k = idx / J, j = idx % J;
                Bs[k][j] = B[(kc + k) * J + j];
            }
        } else {
            for (int idx = tid; idx < KC*J; idx += 256) {
                int j = idx / KC, k = idx % KC;
                Bs[k][j] = B[j * K + kc + k];
            }
        }
        __syncthreads();
#pragma unroll 8
        for (int k = 0; k < KC; k++) {
            float a[TR], b[TC];
#pragma unroll
            for (int i = 0; i < TR; i++) a[i] = As[k][rg*TR + i];
#pragma unroll
            for (int j = 0; j < TC; j++) b[j] = Bs[k][cg*TC + j];
#pragma unroll
            for (int i = 0; i < TR; i++)
#pragma unroll
                for (int j = 0; j < TC; j++)
                    acc[i][j] = fmaf(a[i], b[j], acc[i][j]);
        }
    }
#pragma unroll
    for (int i = 0; i < TR; i++) {
        int r = n0 + rg*TR + i;
        float rs = HASBASE ? (1.f / (float)max(cnt[r], 1)) : 0.f;
#pragma unroll
        for (int j = 0; j < TC; j++) {
            int col = cg*TC + j;
            float v = acc[i][j] + bsh[col];
            if (HASBASE) v += rs * base[(size_t)r*J + col];
            if (RELU) v = fmaxf(v, 0.f);
            C[(size_t)r*J + col] = v;
            if (DUAL) C2[(size_t)r*J + col] = v;
        }
    }
}

// z[n, slice, :] = out[n,:] @ w2[slice]  (slice 64 = b2 bias matrix)
__global__ void zgemm(const float* __restrict__ out, const float* __restrict__ w2,
                      const float* __restrict__ b2, float* __restrict__ z)
{
    __shared__ float As[64][68];
    __shared__ float Bs[64][64];
    const int tid = threadIdx.x;
    const int n0 = blockIdx.x * 64;
    const int d  = blockIdx.y;
    const float* Bsrc = (d < 64) ? (w2 + d * 4096) : b2;
    for (int idx = tid; idx < 4096; idx += 256) {
        As[idx % 64][idx / 64] = out[(size_t)(n0 + idx / 64) * 64 + (idx % 64)];
        Bs[idx / 64][idx % 64] = Bsrc[idx];
    }
    __syncthreads();
    const int rg = tid / 16, cg = tid % 16;
    float acc[4][4];
#pragma unroll
    for (int i = 0; i < 4; i++)
#pragma unroll
        for (int j = 0; j < 4; j++) acc[i][j] = 0.f;
#pragma unroll 8
    for (int k = 0; k < 64; k++) {
        float a[4], b[4];
#pragma unroll
        for (int i = 0; i < 4; i++) a[i] = As[k][rg*4 + i];
#pragma unroll
        for (int j = 0; j < 4; j++) b[j] = Bs[k][cg*4 + j];
#pragma unroll
        for (int i = 0; i < 4; i++)
#pragma unroll
            for (int j = 0; j < 4; j++)
                acc[i][j] = fmaf(a[i], b[j], acc[i][j]);
    }
#pragma unroll
    for (int i = 0; i < 4; i++) {
        float4 v = make_float4(acc[i][0], acc[i][1], acc[i][2], acc[i][3]);
        *(float4*)&z[(size_t)(n0 + rg*4 + i) * ZW + d*64 + cg*4] = v;
    }
}

// ---------- CSR build ----------
__global__ void counts(const int* __restrict__ ei, const int* __restrict__ batch,
                       int* __restrict__ cntd, int* __restrict__ cnts, int* __restrict__ bcnt)
{
    int e = blockIdx.x * 256 + threadIdx.x;
    if (e < EE) {
        atomicAdd(&cnts[ei[e]], 1);
        atomicAdd(&cntd[ei[EE + e]], 1);
    }
    if (e < NN) atomicAdd(&bcnt[batch[e]], 1);
}

__global__ void scan_src(const int* __restrict__ cnt, int* __restrict__ off, int* __restrict__ cur)
{
    __shared__ int part[1024];
    const int t = threadIdx.x;
    int c[4]; int s = 0;
#pragma unroll
    for (int i = 0; i < 4; i++) { c[i] = cnt[t*4 + i]; s += c[i]; }
    part[t] = s;
    __syncthreads();
    for (int st = 1; st < 1024; st <<= 1) {
        int v = (t >= st) ? part[t - st] : 0;
        __syncthreads();
        part[t] += v;
        __syncthreads();
    }
    int base = (t > 0) ? part[t - 1] : 0;
#pragma unroll
    for (int i = 0; i < 4; i++) { off[t*4 + i] = base; cur[t*4 + i] = base; base += c[i]; }
    if (t == 1023) off[NN] = part[1023];
}

__global__ void scatter_edges(const int* __restrict__ ei, int* __restrict__ cur,
                              int* __restrict__ order)
{
    int e = blockIdx.x * 256 + threadIdx.x;
    if (e < EE) {
        int p = atomicAdd(&cur[ei[e]], 1);
        order[p] = e;
    }
}

// ---------- edge messages, one src node per block, z[s] staged in smem ----------
__global__ void edge_msg_csr(const float* __restrict__ hidden, const float* __restrict__ z,
                             const int* __restrict__ ei, const int* __restrict__ off,
                             const int* __restrict__ order, float* __restrict__ agg)
{
    const int s = blockIdx.x;
    const int beg = off[s], end = off[s + 1];
    if (beg == end) return;
    __shared__ float Zs[ZW];
    __shared__ float hsh[8][64];
    const int t = threadIdx.x;
    const float4* zsrc = (const float4*)(z + (size_t)s * ZW);
    for (int i = t; i < ZW/4; i += 256) ((float4*)Zs)[i] = zsrc[i];
    __syncthreads();
    const int w = t >> 5, lane = t & 31;
    for (int idx = beg + w; idx < end; idx += 8) {
        const int e = order[idx];
        hsh[w][lane]      = hidden[(size_t)e*64 + lane];
        hsh[w][lane + 32] = hidden[(size_t)e*64 + 32 + lane];
        __syncwarp();
        float ax = Zs[64*64 + 2*lane], ay = Zs[64*64 + 2*lane + 1];   // bias slice
#pragma unroll 8
        for (int k = 0; k < 64; k++) {
            float h = hsh[w][k];
            float2 v = ((const float2*)Zs)[k*32 + lane];
            ax = fmaf(h, v.x, ax);
            ay = fmaf(h, v.y, ay);
        }
        const int dst = ei[EE + e];
        atomicAdd(&agg[(size_t)dst*64 + 2*lane],     ax);
        atomicAdd(&agg[(size_t)dst*64 + 2*lane + 1], ay);
        __syncwarp();
    }
}

// ---------- DiffGroupNorm ----------
__global__ void dgn_softmax(const float* __restrict__ m, const float* __restrict__ lin,
                            float* __restrict__ s)
{
    __shared__ float msh[64][65];
    __shared__ float lsh[64*GG];
    const int t = threadIdx.x;      // 64 threads
    const int n0 = blockIdx.x * 64;
    for (int r = 0; r < 64; r++) msh[r][t] = m[(size_t)(n0 + r)*64 + t];
    for (int i = t; i < 64*GG; i += 64) lsh[i] = lin[i];
    __syncthreads();
    float logit[GG];
#pragma unroll
    for (int g = 0; g < GG; g++) logit[g] = 0.f;
    for (int k = 0; k < 64; k++) {
        float mv = msh[t][k];
#pragma unroll
        for (int g = 0; g < GG; g++) logit[g] = fmaf(mv, lsh[k*GG + g], logit[g]);
    }
    float mx = logit[0];
#pragma unroll
    for (int g = 1; g < GG; g++) mx = fmaxf(mx, logit[g]);
    float sum = 0.f;
#pragma unroll
    for (int g = 0; g < GG; g++) { logit[g] = expf(logit[g] - mx); sum += logit[g]; }
    float inv = 1.f / sum;
#pragma unroll
    for (int g = 0; g < GG; g++) s[(size_t)(n0 + t)*GG + g] = logit[g] * inv;
}

__global__ void dgn_stats(const float* __restrict__ m, const float* __restrict__ s,
                          const float* __restrict__ gamma, const float* __restrict__ beta,
                          float* __restrict__ inv, float* __restrict__ shift)
{
    const int c = blockIdx.x;               // 0..639
    const int g = c / 64, dd = c % 64;
    float sum = 0.f, sq = 0.f;
    for (int n = threadIdx.x; n < NN; n += 256) {
        float t = s[(size_t)n*GG + g] * m[(size_t)n*64 + dd];
        sum += t; sq = fmaf(t, t, sq);
    }
    __shared__ float rs[256], rq[256];
    rs[threadIdx.x] = sum; rq[threadIdx.x] = sq;
    __syncthreads();
    for (int st = 128; st > 0; st >>= 1) {
        if (threadIdx.x < st) { rs[threadIdx.x] += rs[threadIdx.x + st]; rq[threadIdx.x] += rq[threadIdx.x + st]; }
        __syncthreads();
    }
    if (threadIdx.x == 0) {
        float mu = rs[0] / (float)NN;
        float var = rq[0] / (float)NN - mu*mu;
        float iv = gamma[c] * rsqrtf(var + 1e-5f);
        inv[c] = iv;
        shift[c] = beta[c] - mu * iv;
    }
}

__global__ void dgn_apply(const float* __restrict__ m, const float* __restrict__ s,
                          const float* __restrict__ inv, const float* __restrict__ shift,
                          float* __restrict__ m2)
{
    __shared__ float ssh[64*GG];
    __shared__ float ish[GG*64];
    __shared__ float csh[64];
    const int t = threadIdx.x;
    const int n0 = blockIdx.x * 64;
    for (int i = t; i < 64*GG; i += 256) ssh[i] = s[(size_t)n0*GG + i];
    for (int i = t; i < GG*64; i += 256) ish[i] = inv[i];
    if (t < 64) {
        float cs = 0.f;
#pragma unroll
        for (int g = 0; g < GG; g++) cs += shift[g*64 + t];
        csh[t] = cs;
    }
    __syncthreads();
    for (int idx = t; idx < 4096; idx += 256) {
        int nl = idx / 64, dd = idx % 64;
        float a = 0.f;
#pragma unroll
        for (int g = 0; g < GG; g++) a = fmaf(ssh[nl*GG + g], ish[g*64 + dd], a);
        float mv = m[(size_t)(n0 + nl)*64 + dd];
        float v = mv + 0.01f * fmaf(mv, a, csh[dd]);
        m2[(size_t)(n0 + nl)*64 + dd] = fmaxf(v, 0.f);
    }
}

__global__ void gru_gate(const float* __restrict__ gi, const float* __restrict__ gh,
                         float* __restrict__ h, float* __restrict__ out)
{
    int i = blockIdx.x * 256 + threadIdx.x;
    int n = i >> 6, dd = i & 63;
    const float* gin = gi + (size_t)n*192;
    const float* ghn = gh + (size_t)n*192;
    float r  = 1.f / (1.f + expf(-(gin[dd] + ghn[dd])));
    float zz = 1.f / (1.f + expf(-(gin[64+dd] + ghn[64+dd])));
    float nn = tanhf(fmaf(r, ghn[128+dd], gin[128+dd]));
    float hv = h[i];
    float hnew = fmaf(zz, hv, (1.f - zz) * nn);
    h[i] = hnew;
    out[i] = hnew + out[i];
}

__global__ void pool(const float* __restrict__ out, const int* __restrict__ batch,
                     float* __restrict__ pooled)
{
    int i = blockIdx.x * 256 + threadIdx.x;
    atomicAdd(&pooled[batch[i >> 6]*64 + (i & 63)], out[i]);
}

// one block per graph b: p = relu(pooled/cnt @ postW + postb); y[b] = p @ outW + outb
__global__ void head(const float* __restrict__ pooled, const int* __restrict__ bcnt,
                     const float* __restrict__ postW, const float* __restrict__ postb,
                     const float* __restrict__ outW, const float* __restrict__ outb,
                     float* __restrict__ y)
{
    const int b = blockIdx.x;
    const int j = threadIdx.x;   // 64
    __shared__ float pr[64];
    __shared__ float red[64];
    float invv = 1.f / (float)max(bcnt[b], 1);
    pr[j] = pooled[b*64 + j] * invv;
    __syncthreads();
    float acc = postb[j];
    for (int k = 0; k < 64; k++) acc = fmaf(pr[k], postW[k*64 + j], acc);
    float pv = fmaxf(acc, 0.f) * outW[j];
    red[j] = pv;
    __syncthreads();
    for (int st = 32; st > 0; st >>= 1) {
        if (j < st) red[j] += red[j + st];
        __syncthreads();
    }
    if (j == 0) y[b] = red[0] + outb[0];
}

__global__ void tkl_kernel(const float* __restrict__ preW, const float* __restrict__ preb,
                           const float* __restrict__ postW, const float* __restrict__ postb,
                           const float* __restrict__ outW, const float* __restrict__ outb,
                           float* __restrict__ dst)
{
    const double logc = log(0.15 * sqrt(2.0 * 3.14159265358979323846));
    double acc = 0.0;
    const int tid = threadIdx.x;
    const float* arrs[6] = {preW, preb, postW, postb, outW, outb};
    const int lens[6] = {128*64, 64, 64*64, 64, 64, 1};
    for (int a = 0; a < 6; a++)
        for (int i = tid; i < lens[a]; i += 256) {
            double v = (double)arrs[a][i] / 0.15;
            acc += 0.5 * v * v + logc;
        }
    __shared__ double red[256];
    red[tid] = acc;
    __syncthreads();
    for (int st = 128; st > 0; st >>= 1) {
        if (tid < st) red[tid] += red[tid + st];
        __syncthreads();
    }
    if (tid == 0) dst[0] = (float)red[0];
}

extern "C" void kernel_launch(void* const* d_in, const int* in_sizes, int n_in,
                              void* d_out, int out_size)
{
    const float* x         = (const float*)d_in[0];
    const float* edge_attr = (const float*)d_in[1];
    const float* pre_W     = (const float*)d_in[2];
    const float* pre_b     = (const float*)d_in[3];
    const float* edge_w1   = (const float*)d_in[4];
    const float* edge_b1   = (const float*)d_in[5];
    const float* edge_w2   = (const float*)d_in[6];
    const float* edge_b2   = (const float*)d_in[7];
    const float* root_w    = (const float*)d_in[8];
    const float* root_b    = (const float*)d_in[9];
    const float* gru_wih   = (const float*)d_in[10];
    const float* gru_whh   = (const float*)d_in[11];
    const float* gru_bih   = (const float*)d_in[12];
    const float* gru_bhh   = (const float*)d_in[13];
    const float* gn_lin    = (const float*)d_in[14];
    const float* gn_gamma  = (const float*)d_in[15];
    const float* gn_beta   = (const float*)d_in[16];
    const float* post_W    = (const float*)d_in[17];
    const float* post_b    = (const float*)d_in[18];
    const float* out_W     = (const float*)d_in[19];
    const float* out_b     = (const float*)d_in[20];
    const int*   ei        = (const int*)d_in[21];
    const int*   batch     = (const int*)d_in[22];
    float* y = (float*)d_out;

    float *p_out, *p_h, *p_hidden, *p_z, *p_agg, *p_m, *p_m2, *p_s, *p_inv, *p_shift,
          *p_gi, *p_gh, *p_pooled;
    int *p_cntd, *p_cnts, *p_bcnt, *p_soff, *p_cur, *p_order;
    cudaGetSymbolAddress((void**)&p_out, g_out);
    cudaGetSymbolAddress((void**)&p_h, g_h);
    cudaGetSymbolAddress((void**)&p_hidden, g_hidden);
    cudaGetSymbolAddress((void**)&p_z, g_z);
    cudaGetSymbolAddress((void**)&p_agg, g_agg);
    cudaGetSymbolAddress((void**)&p_m, g_m);
    cudaGetSymbolAddress((void**)&p_m2, g_m2);
    cudaGetSymbolAddress((void**)&p_s, g_s);
    cudaGetSymbolAddress((void**)&p_inv, g_inv);
    cudaGetSymbolAddress((void**)&p_shift, g_shift);
    cudaGetSymbolAddress((void**)&p_gi, g_gi);
    cudaGetSymbolAddress((void**)&p_gh, g_gh);
    cudaGetSymbolAddress((void**)&p_pooled, g_pooled);
    cudaGetSymbolAddress((void**)&p_cntd, g_cntd);
    cudaGetSymbolAddress((void**)&p_cnts, g_cnts);
    cudaGetSymbolAddress((void**)&p_bcnt, g_bcnt);
    cudaGetSymbolAddress((void**)&p_soff, g_soff);
    cudaGetSymbolAddress((void**)&p_cur, g_cur);
    cudaGetSymbolAddress((void**)&p_order, g_order);

    cudaMemsetAsync(p_cntd, 0, NN * sizeof(int));
    cudaMemsetAsync(p_cnts, 0, NN * sizeof(int));
    cudaMemsetAsync(p_bcnt, 0, BB * sizeof(int));
    cudaMemsetAsync(p_pooled, 0, BB * 64 * sizeof(float));

    if (out_size >= 65)
        tkl_kernel<<<1, 256>>>(pre_W, pre_b, post_W, post_b, out_W, out_b, y + 64);

    counts<<<EE/256, 256>>>(ei, batch, p_cntd, p_cnts, p_bcnt);
    scan_src<<<1, 1024>>>(p_cnts, p_soff, p_cur);
    scatter_edges<<<EE/256, 256>>>(ei, p_cur, p_order);

    // pre FC + relu; writes both out and h
    gemm_small<128,64,4,false,true,false,true><<<NN/64, 256>>>(x, pre_W, pre_b, nullptr, nullptr, p_out, p_h);

    for (int i = 0; i < 3; i++) {
        const float* w1 = edge_w1 + (size_t)i*64*64;
        const float* b1 = edge_b1 + (size_t)i*64;
        const float* w2 = edge_w2 + (size_t)i*64*4096;
        const float* b2 = edge_b2 + (size_t)i*4096;

        // hidden = relu(edge_attr @ w1 + b1)
        gemm_small<64,64,4,false,true,false,false><<<EE/64, 256>>>(edge_attr, w1, b1, nullptr, nullptr, p_hidden, nullptr);
        // z[n,slice,:] = out @ w2_slice
        zgemm<<<dim3(NN/64, 65), 256>>>(p_out, w2, b2, p_z);
        // scatter messages, grouped by src
        cudaMemsetAsync(p_agg, 0, NN*64*sizeof(float));
        edge_msg_csr<<<NN, 256>>>(p_hidden, p_z, ei, p_soff, p_order, p_agg);
        // m = agg/cnt + out @ root_w + root_b
        gemm_small<64,64,4,false,false,true,false><<<NN/64, 256>>>(p_out, root_w + (size_t)i*4096,
            root_b + (size_t)i*64, p_agg, p_cntd, p_m, nullptr);
        // DiffGroupNorm + relu
        dgn_softmax<<<NN/64, 64>>>(p_m, gn_lin + (size_t)i*64*GG, p_s);
        dgn_stats<<<GG*64, 256>>>(p_m, p_s, gn_gamma + (size_t)i*GG*64, gn_beta + (size_t)i*GG*64, p_inv, p_shift);
        dgn_apply<<<NN/64, 256>>>(p_m, p_s, p_inv, p_shift, p_m2);
        // GRU
        gemm_small<64,192,12,true,false,false,false><<<NN/64, 256>>>(p_m2, gru_wih + (size_t)i*192*64,
            gru_bih + (size_t)i*192, nullptr, nullptr, p_gi, nullptr);
        gemm_small<64,192,12,true,false,false,false><<<NN/64, 256>>>(p_h, gru_whh + (size_t)i*192*64,
            gru_bhh + (size_t)i*192, nullptr, nullptr, p_gh, nullptr);
        gru_gate<<<NN*64/256, 256>>>(p_gi, p_gh, p_h, p_out);
    }

    pool<<<NN*64/256, 256>>>(p_out, batch, p_pooled);
    head<<<BB, 64>>>(p_pooled, p_bcnt, post_W, post_b, out_W, out_b, y);
}